// round 17
// baseline (speedup 1.0000x reference)
#include <cuda_runtime.h>
#include <cstdint>

#define CELLS (130 * 256 * 256)
#define GUARD 0x00808080

__device__ int g_rowid[CELLS];

__global__ void scatter_rowid(const int* __restrict__ out_pos, int M) {
    int m = blockIdx.x * blockDim.x + threadIdx.x;
    if (m >= M) return;
    int x = out_pos[3 * m + 0];
    int y = out_pos[3 * m + 1];
    int z = out_pos[3 * m + 2];
    g_rowid[(x << 16) | (y << 8) | z] = m;
}

__device__ __forceinline__ int tap_off(int t) {
    int di = t / 9;
    int rem = t - di * 9;
    int dj = rem / 3;
    int dk = rem - dj * 3;
    return (di << 16) | (dj << 8) | dk;
}

__device__ __forceinline__ void cvt_split(float a, uint32_t& hi, uint32_t& lo) {
    asm("cvt.rna.tf32.f32 %0, %1;" : "=r"(hi) : "f"(a));
    float lof = a - __uint_as_float(hi);
    asm("cvt.rna.tf32.f32 %0, %1;" : "=r"(lo) : "f"(lof));
}

__device__ __forceinline__ void mma8(float* c, const uint32_t* a, const uint32_t* b) {
    asm volatile(
        "mma.sync.aligned.m16n8k8.row.col.f32.tf32.tf32.f32 "
        "{%0,%1,%2,%3}, {%4,%5,%6,%7}, {%8,%9}, {%0,%1,%2,%3};"
        : "+f"(c[0]), "+f"(c[1]), "+f"(c[2]), "+f"(c[3])
        : "r"(a[0]), "r"(a[1]), "r"(a[2]), "r"(a[3]), "r"(b[0]), "r"(b[1]));
}

// smem layout (float offsets); strides chosen for conflict-free fragment LDS
#define A_STR 36
#define O_AHI 0
#define O_ALO (128 * A_STR)            // 4608
#define O_B   (2 * 128 * A_STR)        // 9216; slot s: hi @ +s*2304, lo @ +s*2304+1152
#define O_ACC (O_B + 2 * 2304)         // 13824; warp w: +w*1280 ([32 rows][40])
#define O_LS  (O_ACC + 4 * 1280)       // 18944
#define SMEMF (O_LS + 128)             // 19072 floats
#define SMEM_BYTES (SMEMF * 4)         // 76288 bytes

__global__ __launch_bounds__(128)
void mma_conv(const float* __restrict__ feat,
              const int*   __restrict__ in_pos,
              const float* __restrict__ W,
              float*       __restrict__ out,
              int N) {
    extern __shared__ float sm[];
    uint32_t* Ahi = (uint32_t*)(sm + O_AHI);
    uint32_t* Alo = (uint32_t*)(sm + O_ALO);
    uint32_t* Bt  = (uint32_t*)(sm + O_B);
    float*    acc = sm + O_ACC;
    int*      ls  = (int*)(sm + O_LS);

    int tid  = threadIdx.x;
    int warp = tid >> 5;
    int lane = tid & 31;
    int g    = lane >> 2;    // group id (0..7)
    int tg   = lane & 3;     // thread in group

    int base = blockIdx.x * 128;
    int cnt  = min(128, N - base);

    // ---- stage A (feat tile) as tf32 hi/lo ----
    for (int i = tid; i < 4096; i += 128) {
        int r = i >> 5, c = i & 31;
        float a = (r < cnt) ? __ldg(&feat[(size_t)(base + r) * 32 + c]) : 0.0f;
        uint32_t hi, lo;
        cvt_split(a, hi, lo);
        Ahi[r * A_STR + c] = hi;
        Alo[r * A_STR + c] = lo;
    }
    {   // stage packed lids (one per thread)
        int l = 0;
        if (tid < cnt) {
            int idx = base + tid;
            int x = in_pos[3 * idx + 0];
            int y = in_pos[3 * idx + 1];
            int z = in_pos[3 * idx + 2];
            l = (x << 16) | (y << 8) | z;
        }
        ls[tid] = l;
    }
    // ---- stage B[0] (W[0]^T) into slot 0 ----
    {
        uint32_t* bh = Bt;
        uint32_t* bl = Bt + 1152;
        for (int i = tid; i < 1024; i += 128) {
            int f = i & 31, c = i >> 5;
            float b = __ldg(&W[c * 32 + f]);
            uint32_t hi, lo;
            cvt_split(b, hi, lo);
            bh[f * A_STR + c] = hi;
            bl[f * A_STR + c] = lo;
        }
    }
    __syncthreads();

    // ---- hoist A fragments (tap-invariant) ----
    uint32_t aH[2][4][4], aL[2][4][4];
    #pragma unroll
    for (int mt = 0; mt < 2; mt++) {
        int r0 = warp * 32 + mt * 16 + g;
        #pragma unroll
        for (int ks = 0; ks < 4; ks++) {
            int k0 = ks * 8 + tg;
            aH[mt][ks][0] = Ahi[r0 * A_STR + k0];
            aH[mt][ks][1] = Ahi[(r0 + 8) * A_STR + k0];
            aH[mt][ks][2] = Ahi[r0 * A_STR + k0 + 4];
            aH[mt][ks][3] = Ahi[(r0 + 8) * A_STR + k0 + 4];
            aL[mt][ks][0] = Alo[r0 * A_STR + k0];
            aL[mt][ks][1] = Alo[(r0 + 8) * A_STR + k0];
            aL[mt][ks][2] = Alo[r0 * A_STR + k0 + 4];
            aL[mt][ks][3] = Alo[(r0 + 8) * A_STR + k0 + 4];
        }
    }

    float* aw = acc + warp * 1280;   // warp-private [32][40]

    for (int k = 0; k < 27; k++) {
        int slot = k & 1;
        uint32_t* bh = Bt + slot * 2304;
        uint32_t* bl = bh + 1152;

        float c[2][4][4] = {};
        #pragma unroll
        for (int ks = 0; ks < 4; ks++) {
            uint32_t bH[4][2], bL[4][2];
            #pragma unroll
            for (int nt = 0; nt < 4; nt++) {
                int n0 = nt * 8 + g;
                int k0 = ks * 8 + tg;
                bH[nt][0] = bh[n0 * A_STR + k0];
                bH[nt][1] = bh[n0 * A_STR + k0 + 4];
                bL[nt][0] = bl[n0 * A_STR + k0];
                bL[nt][1] = bl[n0 * A_STR + k0 + 4];
            }
            #pragma unroll
            for (int mt = 0; mt < 2; mt++)
                #pragma unroll
                for (int nt = 0; nt < 4; nt++) {
                    mma8(c[mt][nt], aH[mt][ks], bH[nt]);   // hi*hi
                    mma8(c[mt][nt], aH[mt][ks], bL[nt]);   // hi*lo
                    mma8(c[mt][nt], aL[mt][ks], bH[nt]);   // lo*hi
                }
        }

        // fragments -> warp-private smem tile [32 rows][40]
        #pragma unroll
        for (int mt = 0; mt < 2; mt++)
            #pragma unroll
            for (int nt = 0; nt < 4; nt++) {
                int r0  = mt * 16 + g;
                int col = nt * 8 + 2 * tg;
                *(float2*)(aw + r0 * 40 + col)       = make_float2(c[mt][nt][0], c[mt][nt][1]);
                *(float2*)(aw + (r0 + 8) * 40 + col) = make_float2(c[mt][nt][2], c[mt][nt][3]);
            }
        __syncwarp();

        // scatter: one coalesced RED per valid row (lane = feature)
        int off = tap_off(k);
        #pragma unroll 4
        for (int r = 0; r < 32; r++) {
            int prow = warp * 32 + r;
            int df = (ls[prow] | GUARD) - off;
            bool v = ((df & GUARD) == GUARD) && (prow < cnt);
            int cell = min(df ^ GUARD, CELLS - 1);
            int ro = __ldg(&g_rowid[cell]);
            float val = aw[r * 40 + lane];
            if (v) atomicAdd(&out[(size_t)ro * 32 + lane], val);
        }
        __syncwarp();

        // stage B[k+1] into the other slot
        if (k < 26) {
            uint32_t* nh = Bt + (slot ^ 1) * 2304;
            uint32_t* nl = nh + 1152;
            for (int i = tid; i < 1024; i += 128) {
                int f = i & 31, cc = i >> 5;
                float b = __ldg(&W[(k + 1) * 1024 + cc * 32 + f]);
                uint32_t hi, lo;
                cvt_split(b, hi, lo);
                nh[f * A_STR + cc] = hi;
                nl[f * A_STR + cc] = lo;
            }
        }
        __syncthreads();
    }
}

extern "C" void kernel_launch(void* const* d_in, const int* in_sizes, int n_in,
                              void* d_out, int out_size) {
    const float* feat    = (const float*)d_in[0];
    const int*   in_pos  = (const int*)d_in[1];
    const int*   out_pos = (const int*)d_in[2];
    const float* W       = (const float*)d_in[3];
    float* out = (float*)d_out;

    int N = in_sizes[0] / 32;
    int M = in_sizes[2] / 3;

    cudaFuncSetAttribute(mma_conv, cudaFuncAttributeMaxDynamicSharedMemorySize, SMEM_BYTES);

    cudaMemsetAsync(d_out, 0, (size_t)out_size * sizeof(float));
    scatter_rowid<<<(M + 255) / 256, 256>>>(out_pos, M);
    mma_conv<<<(N + 127) / 128, 128, SMEM_BYTES>>>(feat, in_pos, W, out, N);
}